// round 11
// baseline (speedup 1.0000x reference)
#include <cuda_runtime.h>
#include <math.h>
#include <float.h>

#define BB   256
#define CC   128
#define KK   4096
#define NCLSS 100
#define KNNK 8
#define INV_T 14.285714285714286f   // 1/0.07
#define LSE_SHIFT 25.0f             // |dot| <= 1.733 -> |dot|/T <= 24.8

// ---------------- scratch ----------------------------------------------------
__device__ __align__(16) float g_fes[BB*CC];
__device__ __align__(16) float g_fet[BB*CC];
__device__ __align__(16) float g_fgs[BB*CC];
__device__ __align__(16) float g_fgt[BB*CC];
__device__ __align__(16) float g_u [2*BB*NCLSS];
__device__ __align__(16) float g_uT[2*NCLSS*BB];
__device__ int   g_nbr[2*BB*KNNK];
__device__ float g_pos[4*BB];
__device__ float g_psum[4][BB][4];

// ---------------- embed: f_e = l2norm(x @ W^T + b) ---------------------------
template<int D, int ROWS>
__global__ __launch_bounds__(256) void embed_kernel(const float* __restrict__ x,
        const float* __restrict__ W, const float* __restrict__ bias)
{
    __shared__ __align__(16) float xs[ROWS*D];
    __shared__ float outv[CC][ROWS];
    __shared__ float sinv[ROWS];
    float* out = (D == 1024) ? g_fes : g_fet;
    const int t = threadIdx.x, w = t >> 5, lane = t & 31;
    const int g = blockIdx.x;

    const float* xrow = x + (size_t)g*ROWS*D;
    for (int i = t; i < ROWS*D; i += 256) xs[i] = xrow[i];
    __syncthreads();

    const float4* xs4 = (const float4*)xs;
    const float4* W4  = (const float4*)W;
    const int NJ = D/128;

    float acc[16][ROWS];
    #pragma unroll
    for (int cc = 0; cc < 16; cc++)
        #pragma unroll
        for (int r = 0; r < ROWS; r++) acc[cc][r] = 0.f;

    for (int j = 0; j < NJ; j++) {
        float4 xv[ROWS];
        #pragma unroll
        for (int r = 0; r < ROWS; r++) xv[r] = xs4[r*(D/4) + j*32 + lane];
        #pragma unroll
        for (int cc = 0; cc < 16; cc++) {
            const int c = w*16 + cc;
            float4 wv = W4[(size_t)c*(D/4) + j*32 + lane];
            #pragma unroll
            for (int r = 0; r < ROWS; r++)
                acc[cc][r] += wv.x*xv[r].x + wv.y*xv[r].y + wv.z*xv[r].z + wv.w*xv[r].w;
        }
    }

    #pragma unroll
    for (int cc = 0; cc < 16; cc++) {
        const int c = w*16 + cc;
        #pragma unroll
        for (int r = 0; r < ROWS; r++) {
            float v = acc[cc][r];
            #pragma unroll
            for (int o = 16; o; o >>= 1) v += __shfl_xor_sync(0xffffffffu, v, o);
            if (lane == 0) outv[c][r] = v + bias[c];
        }
    }
    __syncthreads();

    if (w < ROWS) {
        float s = 0.f;
        #pragma unroll
        for (int kq = 0; kq < CC/32; kq++) {
            float v = outv[lane + 32*kq][w];
            s += v*v;
        }
        #pragma unroll
        for (int o = 16; o; o >>= 1) s += __shfl_xor_sync(0xffffffffu, s, o);
        if (lane == 0) sinv[w] = rsqrtf(s);
    }
    __syncthreads();

    if (t < CC) {
        #pragma unroll
        for (int r = 0; r < ROWS; r++)
            out[(size_t)(g*ROWS + r)*CC + t] = outv[t][r]*sinv[r];
    }
}

// ---------------- softmax rows, normalized; writes u and uT ------------------
__global__ __launch_bounds__(128) void soft_kernel(const float* __restrict__ ls,
                                                   const float* __restrict__ lt)
{
    const int b = blockIdx.x, which = blockIdx.y;
    const float* l = (which ? lt : ls) + (size_t)b*NCLSS;
    float* u  = g_u  + ((size_t)which*BB + b)*NCLSS;
    const int t = threadIdx.x;
    __shared__ float red[128];

    float v = (t < NCLSS) ? l[t] : -FLT_MAX;
    red[t] = v; __syncthreads();
    for (int off = 64; off > 0; off >>= 1) { if (t < off) red[t] = fmaxf(red[t], red[t+off]); __syncthreads(); }
    float mx = red[0]; __syncthreads();

    float e = (t < NCLSS) ? expf(v - mx) : 0.f;
    red[t] = e*e; __syncthreads();
    for (int off = 64; off > 0; off >>= 1) { if (t < off) red[t] += red[t+off]; __syncthreads(); }
    float inv = rsqrtf(red[0]);
    if (t < NCLSS) {
        float uv = e*inv;
        u[t] = uv;
        g_uT[((size_t)which*NCLSS + t)*BB + b] = uv;
    }
}

// ---------------- knn: 1 query per CTA, 256 threads, coalesced dot -----------
__global__ __launch_bounds__(256) void knn_kernel()
{
    const int i = blockIdx.x, which = blockIdx.y;
    const float* uT = g_uT + (size_t)which*NCLSS*BB;
    const int t = threadIdx.x, lane = t & 31;
    __shared__ float ui[NCLSS];
    __shared__ float val[BB];

    if (t < NCLSS) ui[t] = g_u[((size_t)which*BB + i)*NCLSS + t];
    __syncthreads();

    {
        float v0 = 0.f, v1 = 0.f;
        #pragma unroll 4
        for (int e = 0; e < NCLSS - 1; e += 2) {
            v0 += ui[e]     * uT[(size_t)e*BB + t];
            v1 += ui[e + 1] * uT[(size_t)(e + 1)*BB + t];
        }
        float v = v0 + v1;
        val[t] = (t == i) ? 1.0f : (v - 1.0f);
    }
    __syncthreads();

    if (t < 32) {
        float vv[8];
        #pragma unroll
        for (int q = 0; q < 8; q++) vv[q] = val[lane + 32*q];

        for (int r = 0; r < KNNK; r++) {
            float bv = vv[0]; int bq = 0;
            #pragma unroll
            for (int q = 1; q < 8; q++) if (vv[q] > bv) { bv = vv[q]; bq = q; }
            int bidx = lane + 32*bq;
            #pragma unroll
            for (int o = 16; o; o >>= 1) {
                float ov = __shfl_xor_sync(0xffffffffu, bv, o);
                int   oi = __shfl_xor_sync(0xffffffffu, bidx, o);
                if (ov > bv || (ov == bv && oi < bidx)) { bv = ov; bidx = oi; }
            }
            if (lane == 0) g_nbr[((size_t)which*BB + i)*KNNK + r] = bidx;
            if (lane == (bidx & 31)) vv[bidx >> 5] = -FLT_MAX;
        }
    }
}

// ---------------- gnn_encode: 4 batch rows per CTA ---------------------------
__global__ __launch_bounds__(128) void gnn_kernel(const float* __restrict__ Wgs, const float* __restrict__ bgs,
                                                  const float* __restrict__ Wgt, const float* __restrict__ bgt)
{
    const int g = blockIdx.x, which = blockIdx.y;
    const float* fe  = which ? g_fet : g_fes;
    const float* W   = which ? Wgt : Wgs;
    const float* bias= which ? bgt : bgs;
    float* fg        = which ? g_fgt : g_fgs;
    const int c = threadIdx.x;
    __shared__ float h2[4][2*CC];
    __shared__ float red[CC];
    __shared__ int nb[4][KNNK];

    if (c < 32) {
        int rr = c >> 3, q = c & 7;
        nb[rr][q] = g_nbr[((size_t)which*BB + g*4 + rr)*KNNK + q];
    }
    __syncthreads();

    #pragma unroll
    for (int rr = 0; rr < 4; rr++) {
        h2[rr][c] = fe[(size_t)(g*4 + rr)*CC + c];
        float agg = 0.f;
        #pragma unroll
        for (int q = 0; q < KNNK; q++) agg += fe[(size_t)nb[rr][q]*CC + c];
        h2[rr][CC + c] = agg * (1.0f/KNNK);
    }
    __syncthreads();

    float acc[4];
    float bv = bias[c];
    #pragma unroll
    for (int rr = 0; rr < 4; rr++) acc[rr] = bv;
    #pragma unroll 4
    for (int r = 0; r < 2*CC; r++) {
        float wv = W[(size_t)r*CC + c];
        #pragma unroll
        for (int rr = 0; rr < 4; rr++) acc[rr] += h2[rr][r]*wv;
    }

    for (int rr = 0; rr < 4; rr++) {
        red[c] = acc[rr]*acc[rr]; __syncthreads();
        for (int off = 64; off > 0; off >>= 1) { if (c < off) red[c] += red[c+off]; __syncthreads(); }
        float inv = rsqrtf(red[0]); __syncthreads();
        fg[(size_t)(g*4 + rr)*CC + c] = acc[rr]*inv;
    }
}

// ---------------- smooth + positive logits -----------------------------------
__device__ __forceinline__ float breduce128(float v, float* red, int c)
{
    red[c] = v; __syncthreads();
    for (int off = 64; off > 0; off >>= 1) { if (c < off) red[c] += red[c+off]; __syncthreads(); }
    float r = red[0]; __syncthreads();
    return r;
}

__global__ __launch_bounds__(128) void smooth_pos_kernel(const int* __restrict__ idx,
        const float* __restrict__ mem_l, const float* __restrict__ mem_ab)
{
    const int b = blockIdx.x, c = threadIdx.x;
    __shared__ float red[CC];
    const int id = idx[b];
    float ml  = mem_l [(size_t)id*CC + c];
    float mab = mem_ab[(size_t)id*CC + c];
    float fes = g_fes[(size_t)b*CC + c], fet = g_fet[(size_t)b*CC + c];
    float fgs = g_fgs[(size_t)b*CC + c], fgt = g_fgt[(size_t)b*CC + c];

    float sgs = ml *0.75f + fgs*0.25f;
    float sgt = mab*0.75f + fgt*0.25f;
    sgs *= rsqrtf(breduce128(sgs*sgs, red, c));
    sgt *= rsqrtf(breduce128(sgt*sgt, red, c));

    float ls = breduce128(mab*fes, red, c);
    float lt = breduce128(ml *fet, red, c);
    float gs = breduce128(sgt*fgs, red, c);
    float gt = breduce128(sgs*fgt, red, c);
    if (c == 0) {
        g_pos[0*BB+b] = ls; g_pos[1*BB+b] = lt;
        g_pos[2*BB+b] = gs; g_pos[3*BB+b] = gt;
    }
}

// ---------------- heavy kernel: gathered dual-GEMV + fixed-shift LSE ---------
// grid (BB*4, 2). 16 lanes per row (32 B each), 2 rows per group, 2-stage
// ping-pong. Low register footprint (-> 4 CTAs/SM) to double warp residency.
__device__ __forceinline__ void neg_dots2(const float4* __restrict__ xx,
        const float4* __restrict__ a1, const float4* __restrict__ a2,
        float& d1, float& d2)
{
    d1 = 0.f; d2 = 0.f;
    #pragma unroll
    for (int i = 0; i < 2; i++) {
        d1 += xx[i].x*a1[i].x + xx[i].y*a1[i].y + xx[i].z*a1[i].z + xx[i].w*a1[i].w;
        d2 += xx[i].x*a2[i].x + xx[i].y*a2[i].y + xx[i].z*a2[i].z + xx[i].w*a2[i].w;
    }
}

__global__ __launch_bounds__(256, 4) void neg_kernel(const int* __restrict__ cidx,
        const float* __restrict__ mem_l, const float* __restrict__ mem_ab)
{
    const int b = blockIdx.x >> 2, quarter = blockIdx.x & 3, bank = blockIdx.y;
    const float* mem = bank ? mem_ab : mem_l;
    const float* v1p = (bank ? g_fet : g_fes) + (size_t)b*CC;
    const float* v2p = (bank ? g_fgt : g_fgs) + (size_t)b*CC;
    const int t = threadIdx.x, w = t >> 5, lane = t & 31;
    const int j = lane & 15;    // 32 B segment of the row (float4 j and j+16)
    const int r = lane >> 4;    // row within group of 2

    __shared__ int sidx[1024];
    __shared__ float ss1[8], ss2[8];

    const int* gci = cidx + (size_t)b*KK + quarter*1024;
    for (int i = t; i < 1024; i += 256) sidx[i] = gci[i];

    // lane j owns float4 slots j and j+16 (floats [4j,4j+4) and [64+4j, 64+4j+4))
    float4 a1[2], a2[2];
    a1[0] = ((const float4*)v1p)[j];      a1[1] = ((const float4*)v1p)[j + 16];
    a2[0] = ((const float4*)v2p)[j];      a2[1] = ((const float4*)v2p)[j + 16];
    __syncthreads();

    const int base = w*128;   // this warp's 128 rows: sidx[base + it*2 + r], it<64

    float4 x0[2], x1[2];
    {
        const float4* mp = (const float4*)(mem + (size_t)sidx[base + r]*CC);
        x0[0] = mp[j]; x0[1] = mp[j + 16];
    }
    {
        const float4* mp = (const float4*)(mem + (size_t)sidx[base + 2 + r]*CC);
        x1[0] = mp[j]; x1[1] = mp[j + 16];
    }

    float s1 = 0.f, s2 = 0.f;
    for (int it = 0; it < 64; it += 2) {
        float d1, d2;
        // ---- iteration it (buffer x0) ----
        neg_dots2(x0, a1, a2, d1, d2);
        {   // prefetch rows for it+2 before the shuffle chain
            const float4* mp = (const float4*)(mem + (size_t)sidx[base + (((it+2)&63)<<1) + r]*CC);
            x0[0] = mp[j]; x0[1] = mp[j + 16];
        }
        #pragma unroll
        for (int o = 8; o; o >>= 1) {
            d1 += __shfl_xor_sync(0xffffffffu, d1, o);
            d2 += __shfl_xor_sync(0xffffffffu, d2, o);
        }
        s1 += __expf(fmaf(d1, INV_T, -LSE_SHIFT));
        s2 += __expf(fmaf(d2, INV_T, -LSE_SHIFT));

        // ---- iteration it+1 (buffer x1) ----
        neg_dots2(x1, a1, a2, d1, d2);
        {   // prefetch rows for it+3
            const float4* mp = (const float4*)(mem + (size_t)sidx[base + (((it+3)&63)<<1) + r]*CC);
            x1[0] = mp[j]; x1[1] = mp[j + 16];
        }
        #pragma unroll
        for (int o = 8; o; o >>= 1) {
            d1 += __shfl_xor_sync(0xffffffffu, d1, o);
            d2 += __shfl_xor_sync(0xffffffffu, d2, o);
        }
        s1 += __expf(fmaf(d1, INV_T, -LSE_SHIFT));
        s2 += __expf(fmaf(d2, INV_T, -LSE_SHIFT));
    }

    // warp total: each 16-lane group contributed 16 identical copies -> 1/16 scale
    #pragma unroll
    for (int o = 16; o; o >>= 1) {
        s1 += __shfl_xor_sync(0xffffffffu, s1, o);
        s2 += __shfl_xor_sync(0xffffffffu, s2, o);
    }
    if (lane == 0) { ss1[w] = s1 * 0.0625f; ss2[w] = s2 * 0.0625f; }
    __syncthreads();
    if (t == 0) {
        float S1 = 0.f, S2 = 0.f;
        #pragma unroll
        for (int q = 0; q < 8; q++) { S1 += ss1[q]; S2 += ss2[q]; }
        g_psum[bank][b][quarter]     = S1;
        g_psum[2 + bank][b][quarter] = S2;
    }
}

// ---------------- final reduce -----------------------------------------------
__global__ __launch_bounds__(256) void final_kernel(float* __restrict__ out)
{
    const int t = threadIdx.x;
    __shared__ float red[256];
    float v = 0.f;
    #pragma unroll
    for (int s = 0; s < 4; s++) {
        float p = g_pos[s*BB + t] * INV_T;
        float S = __expf(p - LSE_SHIFT);
        #pragma unroll
        for (int h = 0; h < 4; h++) S += g_psum[s][t][h];
        v += LSE_SHIFT + logf(S) - p;
    }
    red[t] = v; __syncthreads();
    for (int off = 128; off > 0; off >>= 1) { if (t < off) red[t] += red[t+off]; __syncthreads(); }
    if (t == 0) out[0] = red[0] * (1.0f/BB);
}

// ---------------- launch: fork-join overlap (graph-capturable) ---------------
extern "C" void kernel_launch(void* const* d_in, const int* in_sizes, int n_in,
                              void* d_out, int out_size)
{
    const float* f_s   = (const float*)d_in[1];
    const float* l_s   = (const float*)d_in[2];
    const float* f_t   = (const float*)d_in[3];
    const float* l_t   = (const float*)d_in[4];
    const int*   idx   = (const int*)  d_in[5];
    const int*   cidx  = (const int*)  d_in[6];
    const float* W_es  = (const float*)d_in[7];
    const float* b_es  = (const float*)d_in[8];
    const float* W_et  = (const float*)d_in[9];
    const float* b_et  = (const float*)d_in[10];
    const float* W_gs  = (const float*)d_in[11];
    const float* b_gs  = (const float*)d_in[12];
    const float* W_gt  = (const float*)d_in[13];
    const float* b_gt  = (const float*)d_in[14];
    const float* mem_l = (const float*)d_in[15];
    const float* mem_ab= (const float*)d_in[16];
    float* out = (float*)d_out;

    static cudaStream_t sA = nullptr, sB = nullptr, sC = nullptr;
    static cudaEvent_t eRoot = nullptr, eA = nullptr, eB = nullptr, eG = nullptr, eC = nullptr;
    if (sA == nullptr) {
        cudaStreamCreateWithFlags(&sA, cudaStreamNonBlocking);
        cudaStreamCreateWithFlags(&sB, cudaStreamNonBlocking);
        cudaStreamCreateWithFlags(&sC, cudaStreamNonBlocking);
        cudaEventCreateWithFlags(&eRoot, cudaEventDisableTiming);
        cudaEventCreateWithFlags(&eA, cudaEventDisableTiming);
        cudaEventCreateWithFlags(&eB, cudaEventDisableTiming);
        cudaEventCreateWithFlags(&eG, cudaEventDisableTiming);
        cudaEventCreateWithFlags(&eC, cudaEventDisableTiming);
    }

    // fork from the (capturing) default stream
    cudaEventRecord(eRoot, 0);
    cudaStreamWaitEvent(sA, eRoot, 0);
    cudaStreamWaitEvent(sB, eRoot, 0);

    // branch A: embeds
    embed_kernel<1024, 4><<<BB/4, 256, 0, sA>>>(f_s, W_es, b_es);   // -> g_fes
    embed_kernel<2048, 4><<<BB/4, 256, 0, sA>>>(f_t, W_et, b_et);   // -> g_fet
    cudaEventRecord(eA, sA);

    // branch B: softmax -> knn
    soft_kernel<<<dim3(BB, 2), 128, 0, sB>>>(l_s, l_t);             // -> g_u, g_uT
    knn_kernel<<<dim3(BB, 2), 256, 0, sB>>>();                      // -> g_nbr
    cudaEventRecord(eB, sB);

    // join: gnn needs embeds + knn
    cudaStreamWaitEvent(0, eA, 0);
    cudaStreamWaitEvent(0, eB, 0);
    gnn_kernel<<<dim3(BB/4, 2), 128>>>(W_gs, b_gs, W_gt, b_gt);     // -> g_fgs/g_fgt
    cudaEventRecord(eG, 0);

    // branch C: smooth_pos (needs embeds + gnn) runs alongside neg
    cudaStreamWaitEvent(sC, eG, 0);
    smooth_pos_kernel<<<BB, 128, 0, sC>>>(idx, mem_l, mem_ab);      // -> g_pos
    cudaEventRecord(eC, sC);

    // heavy kernel on the main stream
    neg_kernel<<<dim3(BB*4, 2), 256>>>(cidx, mem_l, mem_ab);        // -> g_psum

    // join: final needs neg (main stream order) + smooth (eC)
    cudaStreamWaitEvent(0, eC, 0);
    final_kernel<<<1, 256>>>(out);
}

// round 12
// speedup vs baseline: 1.0004x; 1.0004x over previous
#include <cuda_runtime.h>
#include <math.h>
#include <float.h>

#define BB   256
#define CC   128
#define KK   4096
#define NCLSS 100
#define KNNK 8
#define INV_T 14.285714285714286f   // 1/0.07
#define LSE_SHIFT 25.0f             // |dot| <= 1.733 -> |dot|/T <= 24.8

// ---------------- scratch ----------------------------------------------------
__device__ __align__(16) float g_fes[BB*CC];
__device__ __align__(16) float g_fet[BB*CC];
__device__ __align__(16) float g_fgs[BB*CC];
__device__ __align__(16) float g_fgt[BB*CC];
__device__ __align__(16) float g_u [2*BB*NCLSS];
__device__ __align__(16) float g_uT[2*NCLSS*BB];
__device__ int   g_nbr[2*BB*KNNK];
__device__ float g_pos[4*BB];
__device__ float g_psum[4][BB][4];

// ---------------- embed: f_e = l2norm(x @ W^T + b) ---------------------------
template<int D, int ROWS>
__global__ __launch_bounds__(256) void embed_kernel(const float* __restrict__ x,
        const float* __restrict__ W, const float* __restrict__ bias)
{
    __shared__ __align__(16) float xs[ROWS*D];
    __shared__ float outv[CC][ROWS];
    __shared__ float sinv[ROWS];
    float* out = (D == 1024) ? g_fes : g_fet;
    const int t = threadIdx.x, w = t >> 5, lane = t & 31;
    const int g = blockIdx.x;

    const float* xrow = x + (size_t)g*ROWS*D;
    for (int i = t; i < ROWS*D; i += 256) xs[i] = xrow[i];
    __syncthreads();

    const float4* xs4 = (const float4*)xs;
    const float4* W4  = (const float4*)W;
    const int NJ = D/128;

    float acc[16][ROWS];
    #pragma unroll
    for (int cc = 0; cc < 16; cc++)
        #pragma unroll
        for (int r = 0; r < ROWS; r++) acc[cc][r] = 0.f;

    for (int j = 0; j < NJ; j++) {
        float4 xv[ROWS];
        #pragma unroll
        for (int r = 0; r < ROWS; r++) xv[r] = xs4[r*(D/4) + j*32 + lane];
        #pragma unroll
        for (int cc = 0; cc < 16; cc++) {
            const int c = w*16 + cc;
            float4 wv = W4[(size_t)c*(D/4) + j*32 + lane];
            #pragma unroll
            for (int r = 0; r < ROWS; r++)
                acc[cc][r] += wv.x*xv[r].x + wv.y*xv[r].y + wv.z*xv[r].z + wv.w*xv[r].w;
        }
    }

    #pragma unroll
    for (int cc = 0; cc < 16; cc++) {
        const int c = w*16 + cc;
        #pragma unroll
        for (int r = 0; r < ROWS; r++) {
            float v = acc[cc][r];
            #pragma unroll
            for (int o = 16; o; o >>= 1) v += __shfl_xor_sync(0xffffffffu, v, o);
            if (lane == 0) outv[c][r] = v + bias[c];
        }
    }
    __syncthreads();

    if (w < ROWS) {
        float s = 0.f;
        #pragma unroll
        for (int kq = 0; kq < CC/32; kq++) {
            float v = outv[lane + 32*kq][w];
            s += v*v;
        }
        #pragma unroll
        for (int o = 16; o; o >>= 1) s += __shfl_xor_sync(0xffffffffu, s, o);
        if (lane == 0) sinv[w] = rsqrtf(s);
    }
    __syncthreads();

    if (t < CC) {
        #pragma unroll
        for (int r = 0; r < ROWS; r++)
            out[(size_t)(g*ROWS + r)*CC + t] = outv[t][r]*sinv[r];
    }
}

// ---------------- softmax rows, normalized; writes u and uT ------------------
__global__ __launch_bounds__(128) void soft_kernel(const float* __restrict__ ls,
                                                   const float* __restrict__ lt)
{
    const int b = blockIdx.x, which = blockIdx.y;
    const float* l = (which ? lt : ls) + (size_t)b*NCLSS;
    float* u  = g_u  + ((size_t)which*BB + b)*NCLSS;
    const int t = threadIdx.x;
    __shared__ float red[128];

    float v = (t < NCLSS) ? l[t] : -FLT_MAX;
    red[t] = v; __syncthreads();
    for (int off = 64; off > 0; off >>= 1) { if (t < off) red[t] = fmaxf(red[t], red[t+off]); __syncthreads(); }
    float mx = red[0]; __syncthreads();

    float e = (t < NCLSS) ? expf(v - mx) : 0.f;
    red[t] = e*e; __syncthreads();
    for (int off = 64; off > 0; off >>= 1) { if (t < off) red[t] += red[t+off]; __syncthreads(); }
    float inv = rsqrtf(red[0]);
    if (t < NCLSS) {
        float uv = e*inv;
        u[t] = uv;
        g_uT[((size_t)which*NCLSS + t)*BB + b] = uv;
    }
}

// ---------------- knn: 1 query per CTA, 256 threads, coalesced dot -----------
__global__ __launch_bounds__(256) void knn_kernel()
{
    const int i = blockIdx.x, which = blockIdx.y;
    const float* uT = g_uT + (size_t)which*NCLSS*BB;
    const int t = threadIdx.x, lane = t & 31;
    __shared__ float ui[NCLSS];
    __shared__ float val[BB];

    if (t < NCLSS) ui[t] = g_u[((size_t)which*BB + i)*NCLSS + t];
    __syncthreads();

    {
        float v0 = 0.f, v1 = 0.f;
        #pragma unroll 4
        for (int e = 0; e < NCLSS - 1; e += 2) {
            v0 += ui[e]     * uT[(size_t)e*BB + t];
            v1 += ui[e + 1] * uT[(size_t)(e + 1)*BB + t];
        }
        float v = v0 + v1;
        val[t] = (t == i) ? 1.0f : (v - 1.0f);
    }
    __syncthreads();

    if (t < 32) {
        float vv[8];
        #pragma unroll
        for (int q = 0; q < 8; q++) vv[q] = val[lane + 32*q];

        for (int r = 0; r < KNNK; r++) {
            float bv = vv[0]; int bq = 0;
            #pragma unroll
            for (int q = 1; q < 8; q++) if (vv[q] > bv) { bv = vv[q]; bq = q; }
            int bidx = lane + 32*bq;
            #pragma unroll
            for (int o = 16; o; o >>= 1) {
                float ov = __shfl_xor_sync(0xffffffffu, bv, o);
                int   oi = __shfl_xor_sync(0xffffffffu, bidx, o);
                if (ov > bv || (ov == bv && oi < bidx)) { bv = ov; bidx = oi; }
            }
            if (lane == 0) g_nbr[((size_t)which*BB + i)*KNNK + r] = bidx;
            if (lane == (bidx & 31)) vv[bidx >> 5] = -FLT_MAX;
        }
    }
}

// ---------------- gnn_encode: 4 batch rows per CTA ---------------------------
__global__ __launch_bounds__(128) void gnn_kernel(const float* __restrict__ Wgs, const float* __restrict__ bgs,
                                                  const float* __restrict__ Wgt, const float* __restrict__ bgt)
{
    const int g = blockIdx.x, which = blockIdx.y;
    const float* fe  = which ? g_fet : g_fes;
    const float* W   = which ? Wgt : Wgs;
    const float* bias= which ? bgt : bgs;
    float* fg        = which ? g_fgt : g_fgs;
    const int c = threadIdx.x;
    __shared__ float h2[4][2*CC];
    __shared__ float red[CC];
    __shared__ int nb[4][KNNK];

    if (c < 32) {
        int rr = c >> 3, q = c & 7;
        nb[rr][q] = g_nbr[((size_t)which*BB + g*4 + rr)*KNNK + q];
    }
    __syncthreads();

    #pragma unroll
    for (int rr = 0; rr < 4; rr++) {
        h2[rr][c] = fe[(size_t)(g*4 + rr)*CC + c];
        float agg = 0.f;
        #pragma unroll
        for (int q = 0; q < KNNK; q++) agg += fe[(size_t)nb[rr][q]*CC + c];
        h2[rr][CC + c] = agg * (1.0f/KNNK);
    }
    __syncthreads();

    float acc[4];
    float bv = bias[c];
    #pragma unroll
    for (int rr = 0; rr < 4; rr++) acc[rr] = bv;
    #pragma unroll 4
    for (int r = 0; r < 2*CC; r++) {
        float wv = W[(size_t)r*CC + c];
        #pragma unroll
        for (int rr = 0; rr < 4; rr++) acc[rr] += h2[rr][r]*wv;
    }

    for (int rr = 0; rr < 4; rr++) {
        red[c] = acc[rr]*acc[rr]; __syncthreads();
        for (int off = 64; off > 0; off >>= 1) { if (c < off) red[c] += red[c+off]; __syncthreads(); }
        float inv = rsqrtf(red[0]); __syncthreads();
        fg[(size_t)(g*4 + rr)*CC + c] = acc[rr]*inv;
    }
}

// ---------------- smooth + positive logits -----------------------------------
__device__ __forceinline__ float breduce128(float v, float* red, int c)
{
    red[c] = v; __syncthreads();
    for (int off = 64; off > 0; off >>= 1) { if (c < off) red[c] += red[c+off]; __syncthreads(); }
    float r = red[0]; __syncthreads();
    return r;
}

__global__ __launch_bounds__(128) void smooth_pos_kernel(const int* __restrict__ idx,
        const float* __restrict__ mem_l, const float* __restrict__ mem_ab)
{
    const int b = blockIdx.x, c = threadIdx.x;
    __shared__ float red[CC];
    const int id = idx[b];
    float ml  = mem_l [(size_t)id*CC + c];
    float mab = mem_ab[(size_t)id*CC + c];
    float fes = g_fes[(size_t)b*CC + c], fet = g_fet[(size_t)b*CC + c];
    float fgs = g_fgs[(size_t)b*CC + c], fgt = g_fgt[(size_t)b*CC + c];

    float sgs = ml *0.75f + fgs*0.25f;
    float sgt = mab*0.75f + fgt*0.25f;
    sgs *= rsqrtf(breduce128(sgs*sgs, red, c));
    sgt *= rsqrtf(breduce128(sgt*sgt, red, c));

    float ls = breduce128(mab*fes, red, c);
    float lt = breduce128(ml *fet, red, c);
    float gs = breduce128(sgt*fgs, red, c);
    float gt = breduce128(sgs*fgt, red, c);
    if (c == 0) {
        g_pos[0*BB+b] = ls; g_pos[1*BB+b] = lt;
        g_pos[2*BB+b] = gs; g_pos[3*BB+b] = gt;
    }
}

// ---------------- heavy kernel: gathered dual-GEMV + fixed-shift LSE ---------
// grid (BB*4, 2). 16 lanes per row (32 B each), 2 rows per group, 2-stage
// ping-pong. Low register footprint (-> 4 CTAs/SM) to double warp residency.
__device__ __forceinline__ void neg_dots2(const float4* __restrict__ xx,
        const float4* __restrict__ a1, const float4* __restrict__ a2,
        float& d1, float& d2)
{
    d1 = 0.f; d2 = 0.f;
    #pragma unroll
    for (int i = 0; i < 2; i++) {
        d1 += xx[i].x*a1[i].x + xx[i].y*a1[i].y + xx[i].z*a1[i].z + xx[i].w*a1[i].w;
        d2 += xx[i].x*a2[i].x + xx[i].y*a2[i].y + xx[i].z*a2[i].z + xx[i].w*a2[i].w;
    }
}

__global__ __launch_bounds__(256, 4) void neg_kernel(const int* __restrict__ cidx,
        const float* __restrict__ mem_l, const float* __restrict__ mem_ab)
{
    const int b = blockIdx.x >> 2, quarter = blockIdx.x & 3, bank = blockIdx.y;
    const float* mem = bank ? mem_ab : mem_l;
    const float* v1p = (bank ? g_fet : g_fes) + (size_t)b*CC;
    const float* v2p = (bank ? g_fgt : g_fgs) + (size_t)b*CC;
    const int t = threadIdx.x, w = t >> 5, lane = t & 31;
    const int j = lane & 15;    // 32 B segment of the row (float4 j and j+16)
    const int r = lane >> 4;    // row within group of 2

    __shared__ int sidx[1024];
    __shared__ float ss1[8], ss2[8];

    const int* gci = cidx + (size_t)b*KK + quarter*1024;
    for (int i = t; i < 1024; i += 256) sidx[i] = gci[i];

    // lane j owns float4 slots j and j+16 (floats [4j,4j+4) and [64+4j, 64+4j+4))
    float4 a1[2], a2[2];
    a1[0] = ((const float4*)v1p)[j];      a1[1] = ((const float4*)v1p)[j + 16];
    a2[0] = ((const float4*)v2p)[j];      a2[1] = ((const float4*)v2p)[j + 16];
    __syncthreads();

    const int base = w*128;   // this warp's 128 rows: sidx[base + it*2 + r], it<64

    float4 x0[2], x1[2];
    {
        const float4* mp = (const float4*)(mem + (size_t)sidx[base + r]*CC);
        x0[0] = mp[j]; x0[1] = mp[j + 16];
    }
    {
        const float4* mp = (const float4*)(mem + (size_t)sidx[base + 2 + r]*CC);
        x1[0] = mp[j]; x1[1] = mp[j + 16];
    }

    float s1 = 0.f, s2 = 0.f;
    for (int it = 0; it < 64; it += 2) {
        float d1, d2;
        // ---- iteration it (buffer x0) ----
        neg_dots2(x0, a1, a2, d1, d2);
        {   // prefetch rows for it+2 before the shuffle chain
            const float4* mp = (const float4*)(mem + (size_t)sidx[base + (((it+2)&63)<<1) + r]*CC);
            x0[0] = mp[j]; x0[1] = mp[j + 16];
        }
        #pragma unroll
        for (int o = 8; o; o >>= 1) {
            d1 += __shfl_xor_sync(0xffffffffu, d1, o);
            d2 += __shfl_xor_sync(0xffffffffu, d2, o);
        }
        s1 += __expf(fmaf(d1, INV_T, -LSE_SHIFT));
        s2 += __expf(fmaf(d2, INV_T, -LSE_SHIFT));

        // ---- iteration it+1 (buffer x1) ----
        neg_dots2(x1, a1, a2, d1, d2);
        {   // prefetch rows for it+3
            const float4* mp = (const float4*)(mem + (size_t)sidx[base + (((it+3)&63)<<1) + r]*CC);
            x1[0] = mp[j]; x1[1] = mp[j + 16];
        }
        #pragma unroll
        for (int o = 8; o; o >>= 1) {
            d1 += __shfl_xor_sync(0xffffffffu, d1, o);
            d2 += __shfl_xor_sync(0xffffffffu, d2, o);
        }
        s1 += __expf(fmaf(d1, INV_T, -LSE_SHIFT));
        s2 += __expf(fmaf(d2, INV_T, -LSE_SHIFT));
    }

    // warp total: each 16-lane group contributed 16 identical copies -> 1/16 scale
    #pragma unroll
    for (int o = 16; o; o >>= 1) {
        s1 += __shfl_xor_sync(0xffffffffu, s1, o);
        s2 += __shfl_xor_sync(0xffffffffu, s2, o);
    }
    if (lane == 0) { ss1[w] = s1 * 0.0625f; ss2[w] = s2 * 0.0625f; }
    __syncthreads();
    if (t == 0) {
        float S1 = 0.f, S2 = 0.f;
        #pragma unroll
        for (int q = 0; q < 8; q++) { S1 += ss1[q]; S2 += ss2[q]; }
        g_psum[bank][b][quarter]     = S1;
        g_psum[2 + bank][b][quarter] = S2;
    }
}

// ---------------- final reduce -----------------------------------------------
__global__ __launch_bounds__(256) void final_kernel(float* __restrict__ out)
{
    const int t = threadIdx.x;
    __shared__ float red[256];
    float v = 0.f;
    #pragma unroll
    for (int s = 0; s < 4; s++) {
        float p = g_pos[s*BB + t] * INV_T;
        float S = __expf(p - LSE_SHIFT);
        #pragma unroll
        for (int h = 0; h < 4; h++) S += g_psum[s][t][h];
        v += LSE_SHIFT + logf(S) - p;
    }
    red[t] = v; __syncthreads();
    for (int off = 128; off > 0; off >>= 1) { if (t < off) red[t] += red[t+off]; __syncthreads(); }
    if (t == 0) out[0] = red[0] * (1.0f/BB);
}

// ---------------- launch: fork-join overlap (graph-capturable) ---------------
extern "C" void kernel_launch(void* const* d_in, const int* in_sizes, int n_in,
                              void* d_out, int out_size)
{
    const float* f_s   = (const float*)d_in[1];
    const float* l_s   = (const float*)d_in[2];
    const float* f_t   = (const float*)d_in[3];
    const float* l_t   = (const float*)d_in[4];
    const int*   idx   = (const int*)  d_in[5];
    const int*   cidx  = (const int*)  d_in[6];
    const float* W_es  = (const float*)d_in[7];
    const float* b_es  = (const float*)d_in[8];
    const float* W_et  = (const float*)d_in[9];
    const float* b_et  = (const float*)d_in[10];
    const float* W_gs  = (const float*)d_in[11];
    const float* b_gs  = (const float*)d_in[12];
    const float* W_gt  = (const float*)d_in[13];
    const float* b_gt  = (const float*)d_in[14];
    const float* mem_l = (const float*)d_in[15];
    const float* mem_ab= (const float*)d_in[16];
    float* out = (float*)d_out;

    static cudaStream_t sA = nullptr, sB = nullptr, sC = nullptr;
    static cudaEvent_t eRoot = nullptr, eA = nullptr, eB = nullptr, eG = nullptr, eC = nullptr;
    if (sA == nullptr) {
        cudaStreamCreateWithFlags(&sA, cudaStreamNonBlocking);
        cudaStreamCreateWithFlags(&sB, cudaStreamNonBlocking);
        cudaStreamCreateWithFlags(&sC, cudaStreamNonBlocking);
        cudaEventCreateWithFlags(&eRoot, cudaEventDisableTiming);
        cudaEventCreateWithFlags(&eA, cudaEventDisableTiming);
        cudaEventCreateWithFlags(&eB, cudaEventDisableTiming);
        cudaEventCreateWithFlags(&eG, cudaEventDisableTiming);
        cudaEventCreateWithFlags(&eC, cudaEventDisableTiming);
    }

    // fork from the (capturing) default stream
    cudaEventRecord(eRoot, 0);
    cudaStreamWaitEvent(sA, eRoot, 0);
    cudaStreamWaitEvent(sB, eRoot, 0);

    // branch A: embeds
    embed_kernel<1024, 4><<<BB/4, 256, 0, sA>>>(f_s, W_es, b_es);   // -> g_fes
    embed_kernel<2048, 4><<<BB/4, 256, 0, sA>>>(f_t, W_et, b_et);   // -> g_fet
    cudaEventRecord(eA, sA);

    // branch B: softmax -> knn
    soft_kernel<<<dim3(BB, 2), 128, 0, sB>>>(l_s, l_t);             // -> g_u, g_uT
    knn_kernel<<<dim3(BB, 2), 256, 0, sB>>>();                      // -> g_nbr
    cudaEventRecord(eB, sB);

    // join: gnn needs embeds + knn
    cudaStreamWaitEvent(0, eA, 0);
    cudaStreamWaitEvent(0, eB, 0);
    gnn_kernel<<<dim3(BB/4, 2), 128>>>(W_gs, b_gs, W_gt, b_gt);     // -> g_fgs/g_fgt
    cudaEventRecord(eG, 0);

    // branch C: smooth_pos (needs embeds + gnn) runs alongside neg
    cudaStreamWaitEvent(sC, eG, 0);
    smooth_pos_kernel<<<BB, 128, 0, sC>>>(idx, mem_l, mem_ab);      // -> g_pos
    cudaEventRecord(eC, sC);

    // heavy kernel on the main stream
    neg_kernel<<<dim3(BB*4, 2), 256>>>(cidx, mem_l, mem_ab);        // -> g_psum

    // join: final needs neg (main stream order) + smooth (eC)
    cudaStreamWaitEvent(0, eC, 0);
    final_kernel<<<1, 256>>>(out);
}